// round 1
// baseline (speedup 1.0000x reference)
#include <cuda_runtime.h>
#include <cuda_bf16.h>

#define BB    8
#define NNN   3136
#define DIMM  147
#define NROWS (BB*NNN)          // 25088

// ---------------- scratch (device globals; no allocations) ----------------
__device__ float          g_wT[DIMM*192];          // qkv_w transposed [d][o]
__device__ float          g_projT[64*64];          // [d][o]
__device__ float          g_fc1T[64*64];           // [d][h]
__device__ float          g_fc2T[64*64];           // [h][o]
__device__ __nv_bfloat16  g_qbf[(size_t)NROWS*64]; // q * scale * log2(e), bf16
__device__ __nv_bfloat16  g_kbf[(size_t)NROWS*64]; // k, bf16
__device__ float          g_vf [(size_t)NROWS*64]; // v, fp32 (residual + attn)
__device__ float          g_of [(size_t)NROWS*64]; // attention output, fp32

// ---------------- helpers ----------------
__device__ __forceinline__ void mma16816(float* c, const unsigned* a, const unsigned* b) {
    asm("mma.sync.aligned.m16n8k16.row.col.f32.bf16.bf16.f32 "
        "{%0,%1,%2,%3}, {%4,%5,%6,%7}, {%8,%9}, {%0,%1,%2,%3};"
        : "+f"(c[0]), "+f"(c[1]), "+f"(c[2]), "+f"(c[3])
        : "r"(a[0]), "r"(a[1]), "r"(a[2]), "r"(a[3]), "r"(b[0]), "r"(b[1]));
}

__device__ __forceinline__ unsigned packbf(float lo, float hi) {
    __nv_bfloat162 t = __floats2bfloat162_rn(lo, hi);  // .x = lo (low 16 bits)
    return *reinterpret_cast<unsigned*>(&t);
}

// ---------------- kernel 0: weight transposes ----------------
__global__ void prep_kernel(const float* __restrict__ qkvw, const float* __restrict__ projw,
                            const float* __restrict__ fc1w, const float* __restrict__ fc2w) {
    int stride = gridDim.x * blockDim.x;
    int t0 = blockIdx.x * blockDim.x + threadIdx.x;
    for (int i = t0; i < DIMM*192; i += stride) {
        int d = i / 192, o = i - d*192;
        g_wT[i] = qkvw[o*DIMM + d];
    }
    for (int i = t0; i < 4096; i += stride) {
        int d = i >> 6, o = i & 63;
        g_projT[i] = projw[o*64 + d];
        g_fc1T[i]  = fc1w[o*64 + d];
        g_fc2T[i]  = fc2w[o*64 + d];
    }
}

// ---------------- kernel 1: LN1 + QKV GEMM (32 rows / block) ----------------
// dyn smem: xs[32*148] + ws[147*192] floats = 115840 B
__global__ __launch_bounds__(256) void ln_qkv_kernel(const float* __restrict__ x,
                                                     const float* __restrict__ n1w,
                                                     const float* __restrict__ n1b,
                                                     const float* __restrict__ scale) {
    extern __shared__ float sm1[];
    float* xs = sm1;            // 32 x 148
    float* ws = sm1 + 32*148;   // 147 x 192
    const int tid  = threadIdx.x;
    const int row0 = blockIdx.x * 32;

    for (int i = tid; i < 32*DIMM; i += 256) {
        int r = i / DIMM, d = i - r*DIMM;
        xs[r*148 + d] = x[(size_t)row0*DIMM + i];
    }
    for (int i = tid; i < DIMM*192; i += 256) ws[i] = g_wT[i];
    __syncthreads();

    const int w = tid >> 5, lane = tid & 31;
    #pragma unroll
    for (int rr = 0; rr < 4; rr++) {
        int r = w*4 + rr;
        float s = 0.f, sq = 0.f;
        for (int d = lane; d < DIMM; d += 32) { float v = xs[r*148+d]; s += v; sq += v*v; }
        #pragma unroll
        for (int off = 16; off; off >>= 1) {
            s  += __shfl_xor_sync(0xffffffffu, s,  off);
            sq += __shfl_xor_sync(0xffffffffu, sq, off);
        }
        float mean = s * (1.f/147.f);
        float var  = sq * (1.f/147.f) - mean*mean;
        float rstd = rsqrtf(var + 1e-5f);
        for (int d = lane; d < DIMM; d += 32)
            xs[r*148+d] = (xs[r*148+d] - mean) * rstd * n1w[d] + n1b[d];
    }
    __syncthreads();

    // GEMM: thread -> rows rg*4..+3, outs og + 32k
    const int og = tid & 31, rg = tid >> 5;
    float acc[4][6];
    #pragma unroll
    for (int j = 0; j < 4; j++)
        #pragma unroll
        for (int k = 0; k < 6; k++) acc[j][k] = 0.f;

    for (int d = 0; d < DIMM; d++) {
        float hv[4], wv[6];
        #pragma unroll
        for (int j = 0; j < 4; j++) hv[j] = xs[(rg*4+j)*148 + d];
        #pragma unroll
        for (int k = 0; k < 6; k++) wv[k] = ws[d*192 + og + 32*k];
        #pragma unroll
        for (int j = 0; j < 4; j++)
            #pragma unroll
            for (int k = 0; k < 6; k++) acc[j][k] += hv[j]*wv[k];
    }

    const float qs = scale[0] * 1.4426950408889634f;  // fold scale*log2(e) into q
    #pragma unroll
    for (int j = 0; j < 4; j++) {
        size_t row = (size_t)(row0 + rg*4 + j);
        #pragma unroll
        for (int k = 0; k < 6; k++) {
            int o = og + 32*k;
            float v = acc[j][k];
            if (o < 64)        g_qbf[row*64 + o]       = __float2bfloat16(v * qs);
            else if (o < 128)  g_kbf[row*64 + (o-64)]  = __float2bfloat16(v);
            else               g_vf [row*64 + (o-128)] = v;
        }
    }
}

// ---------------- kernel 2: flash attention, bf16 mma.sync ----------------
// grid (49, 8), 128 threads (4 warps, 16 query rows each)
__global__ __launch_bounds__(128) void attn_kernel() {
    __shared__ __nv_bfloat16 Ks[64*72];  // [j][d], stride 72 -> conflict-free B-frags
    __shared__ __nv_bfloat16 Vt[64*72];  // [d][j], stride 72

    const int tid  = threadIdx.x;
    const int w    = tid >> 5;
    const int lane = tid & 31;
    const int g    = lane >> 2;
    const int tig  = lane & 3;
    const int b    = blockIdx.y;
    const int i0   = blockIdx.x * 64;

    // Q fragments (register-resident for all 49 KV tiles)
    unsigned qa[4][4];
    const __nv_bfloat16* qp = g_qbf + (size_t)(b*NNN + i0 + w*16) * 64;
    #pragma unroll
    for (int kt = 0; kt < 4; kt++) {
        qa[kt][0] = *(const unsigned*)(qp + (g  )*64 + kt*16 + tig*2);
        qa[kt][1] = *(const unsigned*)(qp + (g+8)*64 + kt*16 + tig*2);
        qa[kt][2] = *(const unsigned*)(qp + (g  )*64 + kt*16 + tig*2 + 8);
        qa[kt][3] = *(const unsigned*)(qp + (g+8)*64 + kt*16 + tig*2 + 8);
    }

    float m0 = -1e30f, m1 = -1e30f, l0 = 0.f, l1 = 0.f;
    float o[8][4];
    #pragma unroll
    for (int nt = 0; nt < 8; nt++)
        #pragma unroll
        for (int c = 0; c < 4; c++) o[nt][c] = 0.f;

    for (int jt = 0; jt < 49; jt++) {
        const int j0 = jt * 64;
        // load K tile (bf16, vectorized)
        const unsigned* kp = (const unsigned*)(g_kbf + (size_t)(b*NNN + j0) * 64);
        for (int e = tid; e < 2048; e += 128) {
            int j = e >> 5, d2 = e & 31;
            *(unsigned*)&Ks[j*72 + d2*2] = kp[e];
        }
        // load V tile fp32 -> bf16, transposed into Vt[d][j]
        const float* vp = g_vf + (size_t)(b*NNN + j0) * 64;
        for (int e = tid; e < 2048; e += 128) {
            int j = e >> 5, d2 = e & 31;
            float2 v2 = *(const float2*)(vp + j*64 + d2*2);
            Vt[(d2*2  )*72 + j] = __float2bfloat16(v2.x);
            Vt[(d2*2+1)*72 + j] = __float2bfloat16(v2.y);
        }
        __syncthreads();

        // S = Q K^T  (already includes scale*log2e via q pre-scale)
        float s[8][4];
        #pragma unroll
        for (int nt = 0; nt < 8; nt++) {
            s[nt][0] = s[nt][1] = s[nt][2] = s[nt][3] = 0.f;
            #pragma unroll
            for (int kt = 0; kt < 4; kt++) {
                unsigned bfr[2];
                bfr[0] = *(const unsigned*)&Ks[(nt*8+g)*72 + kt*16 + tig*2];
                bfr[1] = *(const unsigned*)&Ks[(nt*8+g)*72 + kt*16 + tig*2 + 8];
                mma16816(s[nt], qa[kt], bfr);
            }
        }

        // diagonal (self) mask — only when tiles align
        if (jt == blockIdx.x) {
            const int il0 = w*16 + g;
            #pragma unroll
            for (int nt = 0; nt < 8; nt++) {
                int jl = nt*8 + tig*2;
                if (jl   == il0  ) s[nt][0] = -1e30f;
                if (jl+1 == il0  ) s[nt][1] = -1e30f;
                if (jl   == il0+8) s[nt][2] = -1e30f;
                if (jl+1 == il0+8) s[nt][3] = -1e30f;
            }
        }

        // online softmax (base-2)
        float r0 = -1e30f, r1 = -1e30f;
        #pragma unroll
        for (int nt = 0; nt < 8; nt++) {
            r0 = fmaxf(r0, fmaxf(s[nt][0], s[nt][1]));
            r1 = fmaxf(r1, fmaxf(s[nt][2], s[nt][3]));
        }
        r0 = fmaxf(r0, __shfl_xor_sync(0xffffffffu, r0, 1));
        r0 = fmaxf(r0, __shfl_xor_sync(0xffffffffu, r0, 2));
        r1 = fmaxf(r1, __shfl_xor_sync(0xffffffffu, r1, 1));
        r1 = fmaxf(r1, __shfl_xor_sync(0xffffffffu, r1, 2));
        float mn0 = fmaxf(m0, r0), mn1 = fmaxf(m1, r1);
        float a0 = exp2f(m0 - mn0), a1 = exp2f(m1 - mn1);
        m0 = mn0; m1 = mn1;

        float sum0 = 0.f, sum1 = 0.f;
        #pragma unroll
        for (int nt = 0; nt < 8; nt++) {
            s[nt][0] = exp2f(s[nt][0] - mn0);
            s[nt][1] = exp2f(s[nt][1] - mn0);
            s[nt][2] = exp2f(s[nt][2] - mn1);
            s[nt][3] = exp2f(s[nt][3] - mn1);
            sum0 += s[nt][0] + s[nt][1];
            sum1 += s[nt][2] + s[nt][3];
        }
        sum0 += __shfl_xor_sync(0xffffffffu, sum0, 1);
        sum0 += __shfl_xor_sync(0xffffffffu, sum0, 2);
        sum1 += __shfl_xor_sync(0xffffffffu, sum1, 1);
        sum1 += __shfl_xor_sync(0xffffffffu, sum1, 2);
        l0 = l0*a0 + sum0;
        l1 = l1*a1 + sum1;

        #pragma unroll
        for (int nt = 0; nt < 8; nt++) {
            o[nt][0] *= a0; o[nt][1] *= a0;
            o[nt][2] *= a1; o[nt][3] *= a1;
        }

        // pack P -> A fragments (C of m16n8 pairs == A of m16n16)
        unsigned pa[4][4];
        #pragma unroll
        for (int kt2 = 0; kt2 < 4; kt2++) {
            pa[kt2][0] = packbf(s[2*kt2  ][0], s[2*kt2  ][1]);
            pa[kt2][1] = packbf(s[2*kt2  ][2], s[2*kt2  ][3]);
            pa[kt2][2] = packbf(s[2*kt2+1][0], s[2*kt2+1][1]);
            pa[kt2][3] = packbf(s[2*kt2+1][2], s[2*kt2+1][3]);
        }

        // O += P @ V
        #pragma unroll
        for (int nt = 0; nt < 8; nt++) {
            #pragma unroll
            for (int kt2 = 0; kt2 < 4; kt2++) {
                unsigned bfr[2];
                bfr[0] = *(const unsigned*)&Vt[(nt*8+g)*72 + kt2*16 + tig*2];
                bfr[1] = *(const unsigned*)&Vt[(nt*8+g)*72 + kt2*16 + tig*2 + 8];
                mma16816(o[nt], pa[kt2], bfr);
            }
        }
        __syncthreads();
    }

    float inv0 = 1.f / l0, inv1 = 1.f / l1;
    float* op = g_of + (size_t)(b*NNN + i0 + w*16) * 64;
    #pragma unroll
    for (int nt = 0; nt < 8; nt++) {
        *(float2*)(op + (g  )*64 + nt*8 + tig*2) = make_float2(o[nt][0]*inv0, o[nt][1]*inv0);
        *(float2*)(op + (g+8)*64 + nt*8 + tig*2) = make_float2(o[nt][2]*inv1, o[nt][3]*inv1);
    }
}

// ---------------- kernel 3: proj + residual + LN2 + MLP + residual ----------------
// dyn smem: 3*4096 (weights) + 3*2048 (tiles) floats = 73728 B
__global__ __launch_bounds__(256) void mlp_kernel(const float* __restrict__ pb,
                                                  const float* __restrict__ n2w,
                                                  const float* __restrict__ n2b,
                                                  const float* __restrict__ b1,
                                                  const float* __restrict__ b2,
                                                  float* __restrict__ out) {
    extern __shared__ float sm3[];
    float* swp = sm3;
    float* sw1 = sm3 + 4096;
    float* sw2 = sm3 + 8192;
    float* ot  = sm3 + 12288;   // attn out tile; later reused as LN buffer
    float* xa  = ot + 2048;     // x_attn tile
    float* hg  = xa + 2048;     // gelu tile

    const int tid  = threadIdx.x;
    const int row0 = blockIdx.x * 32;

    for (int i = tid; i < 4096; i += 256) {
        swp[i] = g_projT[i];
        sw1[i] = g_fc1T[i];
        sw2[i] = g_fc2T[i];
    }
    for (int i = tid; i < 2048; i += 256) ot[i] = g_of[(size_t)row0*64 + i];
    __syncthreads();

    const int og = tid & 15, rg = tid >> 4;   // 2 rows x 4 outs per thread

    // proj + bias + v residual -> xa
    {
        float acc[2][4];
        #pragma unroll
        for (int r = 0; r < 2; r++)
            #pragma unroll
            for (int k = 0; k < 4; k++) acc[r][k] = 0.f;
        for (int d = 0; d < 64; d++) {
            float a0v = ot[(rg*2  )*64 + d];
            float a1v = ot[(rg*2+1)*64 + d];
            #pragma unroll
            for (int k = 0; k < 4; k++) {
                float wv = swp[d*64 + og + 16*k];
                acc[0][k] += a0v * wv;
                acc[1][k] += a1v * wv;
            }
        }
        #pragma unroll
        for (int rr = 0; rr < 2; rr++) {
            int r = rg*2 + rr;
            #pragma unroll
            for (int k = 0; k < 4; k++) {
                int oo = og + 16*k;
                xa[r*64 + oo] = acc[rr][k] + pb[oo] + g_vf[(size_t)(row0+r)*64 + oo];
            }
        }
    }
    __syncthreads();

    // LN2 -> hb (reuse ot)
    float* hb = ot;
    const int w = tid >> 5, lane = tid & 31;
    #pragma unroll
    for (int rr = 0; rr < 4; rr++) {
        int r = w*4 + rr;
        float v0 = xa[r*64 + lane], v1 = xa[r*64 + lane + 32];
        float s = v0 + v1, sq = v0*v0 + v1*v1;
        #pragma unroll
        for (int off = 16; off; off >>= 1) {
            s  += __shfl_xor_sync(0xffffffffu, s,  off);
            sq += __shfl_xor_sync(0xffffffffu, sq, off);
        }
        float mean = s * (1.f/64.f);
        float var  = sq * (1.f/64.f) - mean*mean;
        float rstd = rsqrtf(var + 1e-5f);
        hb[r*64 + lane]      = (v0 - mean)*rstd*n2w[lane]      + n2b[lane];
        hb[r*64 + lane + 32] = (v1 - mean)*rstd*n2w[lane + 32] + n2b[lane + 32];
    }
    __syncthreads();

    // fc1 + gelu(erf) -> hg
    {
        float acc[2][4];
        #pragma unroll
        for (int r = 0; r < 2; r++)
            #pragma unroll
            for (int k = 0; k < 4; k++) acc[r][k] = 0.f;
        for (int d = 0; d < 64; d++) {
            float a0v = hb[(rg*2  )*64 + d];
            float a1v = hb[(rg*2+1)*64 + d];
            #pragma unroll
            for (int k = 0; k < 4; k++) {
                float wv = sw1[d*64 + og + 16*k];
                acc[0][k] += a0v * wv;
                acc[1][k] += a1v * wv;
            }
        }
        #pragma unroll
        for (int rr = 0; rr < 2; rr++) {
            int r = rg*2 + rr;
            #pragma unroll
            for (int k = 0; k < 4; k++) {
                int oo = og + 16*k;
                float h = acc[rr][k] + b1[oo];
                hg[r*64 + oo] = h * normcdff(h);   // exact GELU: x * Phi(x)
            }
        }
    }
    __syncthreads();

    // fc2 + bias + x_attn residual -> out
    {
        float acc[2][4];
        #pragma unroll
        for (int r = 0; r < 2; r++)
            #pragma unroll
            for (int k = 0; k < 4; k++) acc[r][k] = 0.f;
        for (int d = 0; d < 64; d++) {
            float a0v = hg[(rg*2  )*64 + d];
            float a1v = hg[(rg*2+1)*64 + d];
            #pragma unroll
            for (int k = 0; k < 4; k++) {
                float wv = sw2[d*64 + og + 16*k];
                acc[0][k] += a0v * wv;
                acc[1][k] += a1v * wv;
            }
        }
        #pragma unroll
        for (int rr = 0; rr < 2; rr++) {
            int r = rg*2 + rr;
            #pragma unroll
            for (int k = 0; k < 4; k++) {
                int oo = og + 16*k;
                out[(size_t)(row0+r)*64 + oo] = xa[r*64 + oo] + acc[rr][k] + b2[oo];
            }
        }
    }
}

// ---------------- launch ----------------
extern "C" void kernel_launch(void* const* d_in, const int* in_sizes, int n_in,
                              void* d_out, int out_size) {
    (void)in_sizes; (void)n_in; (void)out_size;
    const float* x     = (const float*)d_in[0];
    const float* n1w   = (const float*)d_in[1];
    const float* n1b   = (const float*)d_in[2];
    const float* qkvw  = (const float*)d_in[3];
    const float* scale = (const float*)d_in[4];
    const float* projw = (const float*)d_in[5];
    const float* projb = (const float*)d_in[6];
    const float* n2w   = (const float*)d_in[7];
    const float* n2b   = (const float*)d_in[8];
    const float* fc1w  = (const float*)d_in[9];
    const float* fc1b  = (const float*)d_in[10];
    const float* fc2w  = (const float*)d_in[11];
    const float* fc2b  = (const float*)d_in[12];
    float* out = (float*)d_out;

    const int K1_SMEM = (32*148 + 147*192) * 4;   // 115840 B
    const int K3_SMEM = (3*4096 + 3*2048) * 4;    // 73728 B
    cudaFuncSetAttribute(ln_qkv_kernel, cudaFuncAttributeMaxDynamicSharedMemorySize, K1_SMEM);
    cudaFuncSetAttribute(mlp_kernel,    cudaFuncAttributeMaxDynamicSharedMemorySize, K3_SMEM);

    prep_kernel<<<64, 256>>>(qkvw, projw, fc1w, fc2w);
    ln_qkv_kernel<<<NROWS/32, 256, K1_SMEM>>>(x, n1w, n1b, scale);
    attn_kernel<<<dim3(49, 8), 128>>>();
    mlp_kernel<<<NROWS/32, 256, K3_SMEM>>>(projb, n2w, n2b, fc1b, fc2b, out);
}